// round 13
// baseline (speedup 1.0000x reference)
#include <cuda_runtime.h>
#include <cuda_fp16.h>

#define RESV 512
#define FULLM 0xffffffffu

typedef unsigned long long u64;

__device__ __forceinline__ void mma16816(float& d0, float& d1, float& d2, float& d3,
                                         unsigned a0, unsigned a1, unsigned a2, unsigned a3,
                                         unsigned b0, unsigned b1) {
    asm volatile("mma.sync.aligned.m16n8k16.row.col.f32.f16.f16.f32 "
                 "{%0,%1,%2,%3},{%4,%5,%6,%7},{%8,%9},{%0,%1,%2,%3};"
                 : "+f"(d0), "+f"(d1), "+f"(d2), "+f"(d3)
                 : "r"(a0), "r"(a1), "r"(a2), "r"(a3), "r"(b0), "r"(b1));
}

__device__ __forceinline__ unsigned packh2(__half lo, __half hi) {
    __half2 h = __halves2half2(lo, hi);
    return *reinterpret_cast<unsigned*>(&h);
}

__device__ __forceinline__ u64 mk_evict_last_policy() {
    u64 pol;
    asm("createpolicy.fractional.L2::evict_last.b64 %0, 1.0;" : "=l"(pol));
    return pol;
}

__device__ __forceinline__ void pf_l2(const void* p) {
    asm volatile("prefetch.global.L2 [%0];" :: "l"(p));
}

// ---- packed f32x2 helpers (Blackwell) ----
__device__ __forceinline__ u64 fma2(u64 a, u64 b, u64 c) {
    u64 d; asm("fma.rn.f32x2 %0, %1, %2, %3;" : "=l"(d) : "l"(a), "l"(b), "l"(c));
    return d;
}
__device__ __forceinline__ u64 add2(u64 a, u64 b) {
    u64 d; asm("add.rn.f32x2 %0, %1, %2;" : "=l"(d) : "l"(a), "l"(b));
    return d;
}
__device__ __forceinline__ u64 bcast2(float v) {
    u64 d; asm("mov.b64 %0, {%1, %1};" : "=l"(d) : "f"(v));
    return d;
}
__device__ __forceinline__ u64 pack2(float lo, float hi) {
    u64 d; asm("mov.b64 %0, {%1, %2};" : "=l"(d) : "f"(lo), "f"(hi));
    return d;
}
__device__ __forceinline__ void unpack2f(u64 v, float& lo, float& hi) {
    asm("mov.b64 {%0, %1}, %2;" : "=f"(lo), "=f"(hi) : "l"(v));
}

// 16-byte plane gather as two packed f32x2 words, evict-last hint
__device__ __forceinline__ ulonglong2 ldg_plane2(const float* p, u64 pol) {
    ulonglong2 v;
    asm volatile("ld.global.nc.L2::cache_hint.v2.u64 {%0,%1}, [%2], %3;"
                 : "=l"(v.x), "=l"(v.y) : "l"(p), "l"(pol));
    return v;
}

// compute clamped cell indices from a raw x value
__device__ __forceinline__ void cell_of(float xv, float& fr, int& q0, int& q1) {
    float pos = (xv + 1.0f) * 0.5f * 511.0f;
    float fl  = floorf(pos);
    fr = pos - fl;
    int q = (int)fl;
    q = q < 0 ? 0 : (q > 511 ? 511 : q);
    q0 = q;
    q1 = (q + 1 > 511) ? 511 : (q + 1);
}

__global__ void __launch_bounds__(256, 3)
styleneus_fused(const float* __restrict__ x,
                const float* __restrict__ planes,
                const float* __restrict__ W1,
                const float* __restrict__ b1,
                const float* __restrict__ W2,
                const float* __restrict__ b2,
                float* __restrict__ out,
                int N)
{
    __shared__ unsigned wfrag[32 * 36];
    __shared__ __half stage[8 * 320];
    __shared__ __align__(16) float uback[256 * 12];

    const __half  sh     = __float2half(0.17677669529663689f);  // fp16(1/sqrt(32))
    const __half  hzero  = __float2half(0.0f);
    const __half2 zero2  = __float2half2_rn(0.0f);
    const __half2 slope2 = __float2half2_rn(0.2f);

    const u64 evlast = mk_evict_last_policy();
    const u64 neg1_2 = 0xBF800000BF800000ULL;  // {-1.0f, -1.0f}

    const int tid  = threadIdx.x;
    const int lane = tid & 31;
    const int f    = lane & 7;   // feature-slice (gather layout)
    const int g    = lane >> 3;  // point-in-pass (gather layout)
    const int tig  = lane & 3;   // mma thread-in-group
    const int gid  = lane >> 2;  // mma group id

    #define W1S(i, j) __hmul(__float2half(__ldg(&W1[(i) * 32 + (j)])), sh)
    #define W2S(i, j) __hmul(__float2half(__ldg(&W2[(i) * 4 + (j)])), sh)

    if (tid < 32) {
        unsigned* wl = wfrag + lane * 36;
        #pragma unroll
        for (int kt = 0; kt < 2; kt++)
            #pragma unroll
            for (int nt = 0; nt < 4; nt++) {
                int k0 = 16 * kt + 2 * tig;
                int jc = 8 * nt + gid;
                wl[kt * 8 + nt * 2 + 0] = packh2(W1S(k0,     jc), W1S(k0 + 1, jc));
                wl[kt * 8 + nt * 2 + 1] = packh2(W1S(k0 + 8, jc), W1S(k0 + 9, jc));
                wl[16 + kt * 8 + nt * 2 + 0] = packh2(W1S(jc, k0),     W1S(jc, k0 + 1));
                wl[16 + kt * 8 + nt * 2 + 1] = packh2(W1S(jc, k0 + 8), W1S(jc, k0 + 9));
            }
        #pragma unroll
        for (int kt = 0; kt < 2; kt++) {
            int k0 = 16 * kt + 2 * tig;
            if (gid < 4) {
                wl[32 + kt * 2 + 0] = packh2(W2S(k0,     gid), W2S(k0 + 1, gid));
                wl[32 + kt * 2 + 1] = packh2(W2S(k0 + 8, gid), W2S(k0 + 9, gid));
            } else {
                wl[32 + kt * 2 + 0] = 0;
                wl[32 + kt * 2 + 1] = 0;
            }
        }
    }
    __syncthreads();

    __half2 b1h2[4], wpos[4];
    #pragma unroll
    for (int nt = 0; nt < 4; nt++) {
        int c0 = 8 * nt + 2 * tig;
        b1h2[nt] = __halves2half2(__float2half(__ldg(&b1[c0])), __float2half(__ldg(&b1[c0 + 1])));
        wpos[nt] = __halves2half2(W2S(c0, 0), W2S(c0 + 1, 0));
    }
    __half2 b2p = zero2;
    if (tig < 2)
        b2p = __halves2half2(__float2half(__ldg(&b2[2 * tig])), __float2half(__ldg(&b2[2 * tig + 1])));

    float* __restrict__ outSdf = out;
    float* __restrict__ outH   = out + (size_t)N;
    float* __restrict__ outNab = out + (size_t)N * 33;
    float* __restrict__ outRgb = out + (size_t)N * 36;

    __half* st = stage + (tid >> 5) * 320;
    const uint4* wl4 = reinterpret_cast<const uint4*>(wfrag + lane * 36);
    ulonglong2*  ubq = reinterpret_cast<ulonglong2*>(uback + tid * 12);

    const int warpsPerCta = blockDim.x >> 5;
    int       warpId      = blockIdx.x * warpsPerCta + (tid >> 5);
    const int warpStride  = gridDim.x * warpsPerCta;

    // ---- preload this warp's first-iteration x values ----
    float xn[2][3];
    if (warpId * 8 < N) {
        #pragma unroll
        for (int r = 0; r < 2; r++) {
            int p  = warpId * 8 + 4 * r + g;
            int pc = (p < N) ? p : (N - 1);
            #pragma unroll
            for (int d = 0; d < 3; d++) xn[r][d] = __ldcs(&x[pc * 3 + d]);
        }
    }

    for (; warpId * 8 < N; warpId += warpStride) {
        const int base = warpId * 8;

        // ---------- indices for this iteration (from carried xn — no stall) ----------
        float fr2[2][3];
        int   i02[2][3], i12[2][3];
        #pragma unroll
        for (int r = 0; r < 2; r++)
            #pragma unroll
            for (int d = 0; d < 3; d++)
                cell_of(xn[r][d], fr2[r][d], i02[r][d], i12[r][d]);

        // ---------- prefetch pass-1 gather lines into L2 (short range, as R11) ----------
        #pragma unroll
        for (int k = 0; k < 3; k++) {
            const int a = (k == 2) ? 1 : 0;
            const int b = (k == 0) ? 1 : 2;
            const float* pb = planes + (size_t)k * (RESV * RESV * 32);
            int ra0 = i02[1][a] << 9, ra1 = i12[1][a] << 9;
            int cb0 = i02[1][b],      cb1 = i12[1][b];
            pf_l2(pb + (((size_t)(ra0 + cb0)) << 5) + 4 * f);
            pf_l2(pb + (((size_t)(ra0 + cb1)) << 5) + 4 * f);
            pf_l2(pb + (((size_t)(ra1 + cb0)) << 5) + 4 * f);
            pf_l2(pb + (((size_t)(ra1 + cb1)) << 5) + 4 * f);
        }

        // ---------- issue next-iteration x loads (land under the encode) ----------
        const int  nw      = warpId + warpStride;
        const bool hasNext = (nw * 8 < N);
        float xnext[2][3];
        if (hasNext) {
            #pragma unroll
            for (int r = 0; r < 2; r++) {
                int p  = nw * 8 + 4 * r + g;
                int pc = (p < N) ? p : (N - 1);
                #pragma unroll
                for (int d = 0; d < 3; d++) xnext[r][d] = __ldcs(&x[pc * 3 + d]);
            }
            // keep the iteration-after-next x line warm
            int nw2 = nw + warpStride;
            if (nw2 * 8 < N) pf_l2(&x[(size_t)(nw2 * 8 + g) * 3]);
        }

        // ---------- encode: 2 passes of 4 points, gather layout, f32x2 math ----------
        u64 U2[3][2];
        #pragma unroll
        for (int r = 0; r < 2; r++) {
            int  p     = base + 4 * r + g;
            bool valid = (p < N);

            u64 hq2[2] = {0ULL, 0ULL};
            #pragma unroll
            for (int d = 0; d < 3; d++) { U2[d][0] = 0ULL; U2[d][1] = 0ULL; }

            #pragma unroll
            for (int k = 0; k < 3; k++) {
                const int a = (k == 2) ? 1 : 0;
                const int b = (k == 0) ? 1 : 2;
                float fa = fr2[r][a], fb = fr2[r][b];
                const float* pb = planes + (size_t)k * (RESV * RESV * 32);
                int ra0 = i02[r][a] << 9, ra1 = i12[r][a] << 9;
                int cb0 = i02[r][b],      cb1 = i12[r][b];

                ulonglong2 c00 = ldg_plane2(pb + (((size_t)(ra0 + cb0)) << 5) + 4 * f, evlast);
                ulonglong2 c01 = ldg_plane2(pb + (((size_t)(ra0 + cb1)) << 5) + 4 * f, evlast);
                ulonglong2 c10 = ldg_plane2(pb + (((size_t)(ra1 + cb0)) << 5) + 4 * f, evlast);
                ulonglong2 c11 = ldg_plane2(pb + (((size_t)(ra1 + cb1)) << 5) + 4 * f, evlast);

                float ofa = 1.0f - fa, ofb = 1.0f - fb;
                u64 w00 = bcast2(ofa * ofb);
                u64 w01 = bcast2(ofa * fb);
                u64 w10 = bcast2(fa * ofb);
                u64 w11 = bcast2(fa * fb);
                u64 fa2 = bcast2(fa);
                u64 fb2 = bcast2(fb);

                const int da = (k == 2) ? 1 : 0;  // dim index of fa
                const int db = (k == 0) ? 1 : 2;  // dim index of fb
                #pragma unroll
                for (int hh = 0; hh < 2; hh++) {
                    u64 a00 = hh ? c00.y : c00.x;
                    u64 a01 = hh ? c01.y : c01.x;
                    u64 a10 = hh ? c10.y : c10.x;
                    u64 a11 = hh ? c11.y : c11.x;

                    hq2[hh] = fma2(w00, a00, hq2[hh]);
                    hq2[hh] = fma2(w01, a01, hq2[hh]);
                    hq2[hh] = fma2(w10, a10, hq2[hh]);
                    hq2[hh] = fma2(w11, a11, hq2[hh]);

                    u64 e1 = fma2(neg1_2, a00, a10);
                    u64 e2 = fma2(neg1_2, a01, a11);
                    u64 t1 = fma2(neg1_2, e1, e2);
                    u64 dua = fma2(fb2, t1, e1);
                    u64 e3 = fma2(neg1_2, a00, a01);
                    u64 e4 = fma2(neg1_2, a10, a11);
                    u64 t2 = fma2(neg1_2, e3, e4);
                    u64 dub = fma2(fa2, t2, e3);

                    U2[da][hh] = add2(U2[da][hh], dua);
                    U2[db][hh] = add2(U2[db][hh], dub);
                }
            }

            float h0f, h1f, h2f, h3f;
            unpack2f(hq2[0], h0f, h1f);
            unpack2f(hq2[1], h2f, h3f);

            if (valid) {
                float4 hv = make_float4(h0f, h1f, h2f, h3f);
                __stcs(reinterpret_cast<float4*>(outH + (size_t)p * 32 + 4 * f), hv);
            }

            unsigned hp0 = packh2(__float2half(h0f), __float2half(h1f));
            unsigned hp1 = packh2(__float2half(h2f), __float2half(h3f));
            *reinterpret_cast<uint2*>(st + (4 * r + g) * 40 + 4 * f) = make_uint2(hp0, hp1);

            if (r == 0) {
                ubq[0] = make_ulonglong2(U2[0][0], U2[0][1]);
                ubq[1] = make_ulonglong2(U2[1][0], U2[1][1]);
                ubq[2] = make_ulonglong2(U2[2][0], U2[2][1]);
            }
        }
        __syncwarp();

        // carry next x into xn (registers only)
        if (hasNext) {
            #pragma unroll
            for (int r = 0; r < 2; r++)
                #pragma unroll
                for (int d = 0; d < 3; d++) xn[r][d] = xnext[r][d];
        }

        // ---------- forward mma: Z[8,32] = H * W1s ----------
        unsigned aF[2][2];
        #pragma unroll
        for (int kt = 0; kt < 2; kt++) {
            aF[kt][0] = *reinterpret_cast<const unsigned*>(st + gid * 40 + 2 * tig + 16 * kt);
            aF[kt][1] = *reinterpret_cast<const unsigned*>(st + gid * 40 + 2 * tig + 16 * kt + 8);
        }
        unsigned wfb[16];
        *reinterpret_cast<uint4*>(wfb +  0) = wl4[0];
        *reinterpret_cast<uint4*>(wfb +  4) = wl4[1];
        *reinterpret_cast<uint4*>(wfb +  8) = wl4[2];
        *reinterpret_cast<uint4*>(wfb + 12) = wl4[3];
        float dF[4][4];
        #pragma unroll
        for (int nt = 0; nt < 4; nt++) {
            dF[nt][0] = dF[nt][1] = dF[nt][2] = dF[nt][3] = 0.0f;
            #pragma unroll
            for (int kt = 0; kt < 2; kt++)
                mma16816(dF[nt][0], dF[nt][1], dF[nt][2], dF[nt][3],
                         aF[kt][0], 0u, aF[kt][1], 0u,
                         wfb[kt * 8 + nt * 2], wfb[kt * 8 + nt * 2 + 1]);
        }

        // ---------- activation + cotangent (C layout) ----------
        unsigned y2[4], g2[4];
        #pragma unroll
        for (int nt = 0; nt < 4; nt++) {
            __half2 z2 = __floats2half2_rn(dF[nt][0], dF[nt][1]);
            __half2 yb = __hadd2(z2, b1h2[nt]);
            __half2 yl = __hfma2(__hmin2(yb, zero2), slope2, __hmax2(yb, zero2));
            y2[nt] = *reinterpret_cast<unsigned*>(&yl);
            __half2 wneg = __hmul2(slope2, wpos[nt]);
            __half glo = __hlt(__low2half(yb),  hzero) ? __low2half(wneg)  : __low2half(wpos[nt]);
            __half ghi = __hlt(__high2half(yb), hzero) ? __high2half(wneg) : __high2half(wpos[nt]);
            g2[nt] = packh2(glo, ghi);
        }

        // ---------- layer 2: O[8,4] = Y * W2s ----------
        float o0 = 0, o1 = 0, o2d = 0, o3d = 0;
        {
            uint4 w2f = wl4[8];
            mma16816(o0, o1, o2d, o3d, y2[0], 0u, y2[1], 0u, w2f.x, w2f.y);
            mma16816(o0, o1, o2d, o3d, y2[2], 0u, y2[3], 0u, w2f.z, w2f.w);
        }

        // ---------- backward: GH[8,32] = G * W1s^T ----------
        unsigned wbb[16];
        *reinterpret_cast<uint4*>(wbb +  0) = wl4[4];
        *reinterpret_cast<uint4*>(wbb +  4) = wl4[5];
        *reinterpret_cast<uint4*>(wbb +  8) = wl4[6];
        *reinterpret_cast<uint4*>(wbb + 12) = wl4[7];
        float dB[4][4];
        #pragma unroll
        for (int nt = 0; nt < 4; nt++) {
            dB[nt][0] = dB[nt][1] = dB[nt][2] = dB[nt][3] = 0.0f;
            #pragma unroll
            for (int kt = 0; kt < 2; kt++)
                mma16816(dB[nt][0], dB[nt][1], dB[nt][2], dB[nt][3],
                         g2[2 * kt], 0u, g2[2 * kt + 1], 0u,
                         wbb[kt * 8 + nt * 2], wbb[kt * 8 + nt * 2 + 1]);
        }
        __syncwarp();

        #pragma unroll
        for (int nt = 0; nt < 4; nt++) {
            unsigned pk = packh2(__float2half(dB[nt][0]), __float2half(dB[nt][1]));
            *reinterpret_cast<unsigned*>(st + gid * 40 + 8 * nt + 2 * tig) = pk;
        }
        __syncwarp();

        // ---------- nablas: gh . U per pass (f32x2), reduce over 8 lanes ----------
        float nb[2][3];
        #pragma unroll
        for (int r = 0; r < 2; r++) {
            uint2 gw = *reinterpret_cast<const uint2*>(st + (4 * r + g) * 40 + 4 * f);
            float2 g01f = __half22float2(*reinterpret_cast<__half2*>(&gw.x));
            float2 g23f = __half22float2(*reinterpret_cast<__half2*>(&gw.y));
            u64 g01 = pack2(g01f.x, g01f.y);
            u64 g23 = pack2(g23f.x, g23f.y);
            #pragma unroll
            for (int d = 0; d < 3; d++) {
                u64 u0, u1;
                if (r == 0) { ulonglong2 uq = ubq[d]; u0 = uq.x; u1 = uq.y; }
                else        { u0 = U2[d][0]; u1 = U2[d][1]; }
                u64 s2 = fma2(g01, u0, fma2(g23, u1, 0ULL));
                float slo, shi;
                unpack2f(s2, slo, shi);
                nb[r][d] = slo + shi;
            }
        }
        __syncwarp();

        // reduce-scatter over 8 lanes
        {
            float v0 = nb[0][0], v1 = nb[0][1], v2 = nb[0][2], v3 = 0.0f;
            float v4 = nb[1][0], v5 = nb[1][1], v6 = nb[1][2], v7 = 0.0f;
            bool hi4 = (f & 4) != 0;
            float t;
            t = __shfl_xor_sync(FULLM, hi4 ? v0 : v4, 4, 8); if (hi4) v4 += t; else v0 += t;
            t = __shfl_xor_sync(FULLM, hi4 ? v1 : v5, 4, 8); if (hi4) v5 += t; else v1 += t;
            t = __shfl_xor_sync(FULLM, hi4 ? v2 : v6, 4, 8); if (hi4) v6 += t; else v2 += t;
            float w0 = hi4 ? v4 : v0, w1 = hi4 ? v5 : v1, w2 = hi4 ? v6 : v2, w3 = hi4 ? v7 : v3;
            bool hi2 = (f & 2) != 0;
            t = __shfl_xor_sync(FULLM, hi2 ? w0 : w2, 2, 8); if (hi2) w2 += t; else w0 += t;
            t = __shfl_xor_sync(FULLM, hi2 ? w1 : w3, 2, 8); if (hi2) w3 += t; else w1 += t;
            float u0 = hi2 ? w2 : w0, u1 = hi2 ? w3 : w1;
            bool hi1 = (f & 1) != 0;
            t = __shfl_xor_sync(FULLM, hi1 ? u0 : u1, 1, 8); if (hi1) u1 += t; else u0 += t;
            float res = hi1 ? u1 : u0;

            int fm = f & 3;
            if (fm < 3) {
                int pp = base + ((f >> 2) << 2) + g;
                if (pp < N) __stcs(&outNab[(size_t)pp * 3 + fm], res * 511.0f);
            }
        }

        // ---------- sdf / rgb ----------
        if (tig < 2) {
            int pp = base + gid;
            if (pp < N) {
                __half2 oa = __hadd2(__floats2half2_rn(o0, o1), b2p);
                float a0 = __half2float(__low2half(oa));
                float a1 = __half2float(__high2half(oa));
                if (tig == 0) {
                    __stcs(&outSdf[pp], a0);
                    __stcs(&outRgb[(size_t)pp * 3 + 0], (tanhf(a1) + 1.0f) * 0.5f);
                } else {
                    __stcs(&outRgb[(size_t)pp * 3 + 1], (tanhf(a0) + 1.0f) * 0.5f);
                    __stcs(&outRgb[(size_t)pp * 3 + 2], (tanhf(a1) + 1.0f) * 0.5f);
                }
            }
        }
    }
    #undef W1S
    #undef W2S
}

extern "C" void kernel_launch(void* const* d_in, const int* in_sizes, int n_in,
                              void* d_out, int out_size)
{
    const float* x      = (const float*)d_in[0];
    const float* planes = (const float*)d_in[1];
    const float* W1     = (const float*)d_in[2];
    const float* b1     = (const float*)d_in[3];
    const float* W2     = (const float*)d_in[4];
    const float* b2     = (const float*)d_in[5];
    float* out = (float*)d_out;

    int N = in_sizes[0] / 3;

    const int threads = 256;
    const int ptsPerCta = (threads / 32) * 8;  // 64 points per CTA iteration
    int blocksFull = (N + ptsPerCta - 1) / ptsPerCta;
    int blocks = blocksFull < 4736 ? blocksFull : 4736;

    styleneus_fused<<<blocks, threads>>>(x, planes, W1, b1, W2, b2, out, N);
}

// round 14
// speedup vs baseline: 1.2029x; 1.2029x over previous
#include <cuda_runtime.h>
#include <cuda_fp16.h>

#define RESV 512
#define FULLM 0xffffffffu

typedef unsigned long long u64;

__device__ __forceinline__ void mma16816(float& d0, float& d1, float& d2, float& d3,
                                         unsigned a0, unsigned a1, unsigned a2, unsigned a3,
                                         unsigned b0, unsigned b1) {
    asm volatile("mma.sync.aligned.m16n8k16.row.col.f32.f16.f16.f32 "
                 "{%0,%1,%2,%3},{%4,%5,%6,%7},{%8,%9},{%0,%1,%2,%3};"
                 : "+f"(d0), "+f"(d1), "+f"(d2), "+f"(d3)
                 : "r"(a0), "r"(a1), "r"(a2), "r"(a3), "r"(b0), "r"(b1));
}

__device__ __forceinline__ unsigned packh2(__half lo, __half hi) {
    __half2 h = __halves2half2(lo, hi);
    return *reinterpret_cast<unsigned*>(&h);
}

__device__ __forceinline__ u64 mk_evict_last_policy() {
    u64 pol;
    asm("createpolicy.fractional.L2::evict_last.b64 %0, 1.0;" : "=l"(pol));
    return pol;
}

__device__ __forceinline__ void pf_l2(const void* p) {
    asm volatile("prefetch.global.L2 [%0];" :: "l"(p));
}

// 4-byte async copy global -> shared (no destination registers)
__device__ __forceinline__ void cp_async4(unsigned dst_smem, const void* src) {
    asm volatile("cp.async.ca.shared.global [%0], [%1], 4;" :: "r"(dst_smem), "l"(src));
}
__device__ __forceinline__ void cp_async_commit() {
    asm volatile("cp.async.commit_group;");
}
__device__ __forceinline__ void cp_async_wait0() {
    asm volatile("cp.async.wait_group 0;");
}

// ---- packed f32x2 helpers (Blackwell) ----
__device__ __forceinline__ u64 fma2(u64 a, u64 b, u64 c) {
    u64 d; asm("fma.rn.f32x2 %0, %1, %2, %3;" : "=l"(d) : "l"(a), "l"(b), "l"(c));
    return d;
}
__device__ __forceinline__ u64 add2(u64 a, u64 b) {
    u64 d; asm("add.rn.f32x2 %0, %1, %2;" : "=l"(d) : "l"(a), "l"(b));
    return d;
}
__device__ __forceinline__ u64 bcast2(float v) {
    u64 d; asm("mov.b64 %0, {%1, %1};" : "=l"(d) : "f"(v));
    return d;
}
__device__ __forceinline__ u64 pack2(float lo, float hi) {
    u64 d; asm("mov.b64 %0, {%1, %2};" : "=l"(d) : "f"(lo), "f"(hi));
    return d;
}
__device__ __forceinline__ void unpack2f(u64 v, float& lo, float& hi) {
    asm("mov.b64 {%0, %1}, %2;" : "=f"(lo), "=f"(hi) : "l"(v));
}

// 16-byte plane gather as two packed f32x2 words, evict-last hint
__device__ __forceinline__ ulonglong2 ldg_plane2(const float* p, u64 pol) {
    ulonglong2 v;
    asm volatile("ld.global.nc.L2::cache_hint.v2.u64 {%0,%1}, [%2], %3;"
                 : "=l"(v.x), "=l"(v.y) : "l"(p), "l"(pol));
    return v;
}

// compute clamped cell indices from a raw x value
__device__ __forceinline__ void cell_of(float xv, float& fr, int& q0, int& q1) {
    float pos = (xv + 1.0f) * 0.5f * 511.0f;
    float fl  = floorf(pos);
    fr = pos - fl;
    int q = (int)fl;
    q = q < 0 ? 0 : (q > 511 ? 511 : q);
    q0 = q;
    q1 = (q + 1 > 511) ? 511 : (q + 1);
}

__global__ void __launch_bounds__(256, 3)
styleneus_fused(const float* __restrict__ x,
                const float* __restrict__ planes,
                const float* __restrict__ W1,
                const float* __restrict__ b1,
                const float* __restrict__ W2,
                const float* __restrict__ b2,
                float* __restrict__ out,
                int N)
{
    __shared__ unsigned wfrag[32 * 36];
    __shared__ __half stage[8 * 320];
    __shared__ __align__(16) float uback[256 * 12];
    // double-buffered x staging: [buf][warp][point 0..7][4 floats (3 used)]
    __shared__ __align__(16) float xstage[2][8][8][4];

    const __half  sh     = __float2half(0.17677669529663689f);  // fp16(1/sqrt(32))
    const __half  hzero  = __float2half(0.0f);
    const __half2 zero2  = __float2half2_rn(0.0f);
    const __half2 slope2 = __float2half2_rn(0.2f);

    const u64 evlast = mk_evict_last_policy();
    const u64 neg1_2 = 0xBF800000BF800000ULL;  // {-1.0f, -1.0f}

    const int tid  = threadIdx.x;
    const int lane = tid & 31;
    const int f    = lane & 7;   // feature-slice (gather layout)
    const int g    = lane >> 3;  // point-in-pass (gather layout)
    const int tig  = lane & 3;   // mma thread-in-group
    const int gid  = lane >> 2;  // mma group id
    const int w    = tid >> 5;   // warp in CTA

    #define W1S(i, j) __hmul(__float2half(__ldg(&W1[(i) * 32 + (j)])), sh)
    #define W2S(i, j) __hmul(__float2half(__ldg(&W2[(i) * 4 + (j)])), sh)

    if (tid < 32) {
        unsigned* wl = wfrag + lane * 36;
        #pragma unroll
        for (int kt = 0; kt < 2; kt++)
            #pragma unroll
            for (int nt = 0; nt < 4; nt++) {
                int k0 = 16 * kt + 2 * tig;
                int jc = 8 * nt + gid;
                wl[kt * 8 + nt * 2 + 0] = packh2(W1S(k0,     jc), W1S(k0 + 1, jc));
                wl[kt * 8 + nt * 2 + 1] = packh2(W1S(k0 + 8, jc), W1S(k0 + 9, jc));
                wl[16 + kt * 8 + nt * 2 + 0] = packh2(W1S(jc, k0),     W1S(jc, k0 + 1));
                wl[16 + kt * 8 + nt * 2 + 1] = packh2(W1S(jc, k0 + 8), W1S(jc, k0 + 9));
            }
        #pragma unroll
        for (int kt = 0; kt < 2; kt++) {
            int k0 = 16 * kt + 2 * tig;
            if (gid < 4) {
                wl[32 + kt * 2 + 0] = packh2(W2S(k0,     gid), W2S(k0 + 1, gid));
                wl[32 + kt * 2 + 1] = packh2(W2S(k0 + 8, gid), W2S(k0 + 9, gid));
            } else {
                wl[32 + kt * 2 + 0] = 0;
                wl[32 + kt * 2 + 1] = 0;
            }
        }
    }
    __syncthreads();

    __half2 b1h2[4], wpos[4];
    #pragma unroll
    for (int nt = 0; nt < 4; nt++) {
        int c0 = 8 * nt + 2 * tig;
        b1h2[nt] = __halves2half2(__float2half(__ldg(&b1[c0])), __float2half(__ldg(&b1[c0 + 1])));
        wpos[nt] = __halves2half2(W2S(c0, 0), W2S(c0 + 1, 0));
    }
    __half2 b2p = zero2;
    if (tig < 2)
        b2p = __halves2half2(__float2half(__ldg(&b2[2 * tig])), __float2half(__ldg(&b2[2 * tig + 1])));

    float* __restrict__ outSdf = out;
    float* __restrict__ outH   = out + (size_t)N;
    float* __restrict__ outNab = out + (size_t)N * 33;
    float* __restrict__ outRgb = out + (size_t)N * 36;

    __half* st = stage + w * 320;
    const uint4* wl4 = reinterpret_cast<const uint4*>(wfrag + lane * 36);
    ulonglong2*  ubq = reinterpret_cast<ulonglong2*>(uback + tid * 12);

    const int warpsPerCta = blockDim.x >> 5;
    int       warpId      = blockIdx.x * warpsPerCta + w;
    const int warpStride  = gridDim.x * warpsPerCta;

    int buf = 0;

    // ---- prologue: stage first iteration's x via cp.async ----
    if (warpId * 8 < N) {
        if (f < 3) {
            #pragma unroll
            for (int r = 0; r < 2; r++) {
                int p  = warpId * 8 + 4 * r + g;
                int pc = (p < N) ? p : (N - 1);
                unsigned dst = (unsigned)__cvta_generic_to_shared(&xstage[0][w][4 * r + g][f]);
                cp_async4(dst, &x[(size_t)pc * 3 + f]);
            }
        }
        cp_async_commit();
    }

    for (; warpId * 8 < N; warpId += warpStride) {
        const int base = warpId * 8;

        // ---------- read this iteration's x from smem (cp.async staged) ----------
        cp_async_wait0();
        __syncwarp();
        float4 xv0 = *reinterpret_cast<const float4*>(&xstage[buf][w][g][0]);
        float4 xv1 = *reinterpret_cast<const float4*>(&xstage[buf][w][4 + g][0]);

        float fr2[2][3];
        int   i02[2][3], i12[2][3];
        cell_of(xv0.x, fr2[0][0], i02[0][0], i12[0][0]);
        cell_of(xv0.y, fr2[0][1], i02[0][1], i12[0][1]);
        cell_of(xv0.z, fr2[0][2], i02[0][2], i12[0][2]);
        cell_of(xv1.x, fr2[1][0], i02[1][0], i12[1][0]);
        cell_of(xv1.y, fr2[1][1], i02[1][1], i12[1][1]);
        cell_of(xv1.z, fr2[1][2], i02[1][2], i12[1][2]);

        // ---------- prefetch pass-1 gather lines into L2 (short range, as R11) ----------
        #pragma unroll
        for (int k = 0; k < 3; k++) {
            const int a = (k == 2) ? 1 : 0;
            const int b = (k == 0) ? 1 : 2;
            const float* pb = planes + (size_t)k * (RESV * RESV * 32);
            int ra0 = i02[1][a] << 9, ra1 = i12[1][a] << 9;
            int cb0 = i02[1][b],      cb1 = i12[1][b];
            pf_l2(pb + (((size_t)(ra0 + cb0)) << 5) + 4 * f);
            pf_l2(pb + (((size_t)(ra0 + cb1)) << 5) + 4 * f);
            pf_l2(pb + (((size_t)(ra1 + cb0)) << 5) + 4 * f);
            pf_l2(pb + (((size_t)(ra1 + cb1)) << 5) + 4 * f);
        }

        // ---------- encode: 2 passes of 4 points, gather layout, f32x2 math ----------
        u64 U2[3][2];
        #pragma unroll
        for (int r = 0; r < 2; r++) {
            int  p     = base + 4 * r + g;
            bool valid = (p < N);

            u64 hq2[2] = {0ULL, 0ULL};
            #pragma unroll
            for (int d = 0; d < 3; d++) { U2[d][0] = 0ULL; U2[d][1] = 0ULL; }

            #pragma unroll
            for (int k = 0; k < 3; k++) {
                const int a = (k == 2) ? 1 : 0;
                const int b = (k == 0) ? 1 : 2;
                float fa = fr2[r][a], fb = fr2[r][b];
                const float* pb = planes + (size_t)k * (RESV * RESV * 32);
                int ra0 = i02[r][a] << 9, ra1 = i12[r][a] << 9;
                int cb0 = i02[r][b],      cb1 = i12[r][b];

                ulonglong2 c00 = ldg_plane2(pb + (((size_t)(ra0 + cb0)) << 5) + 4 * f, evlast);
                ulonglong2 c01 = ldg_plane2(pb + (((size_t)(ra0 + cb1)) << 5) + 4 * f, evlast);
                ulonglong2 c10 = ldg_plane2(pb + (((size_t)(ra1 + cb0)) << 5) + 4 * f, evlast);
                ulonglong2 c11 = ldg_plane2(pb + (((size_t)(ra1 + cb1)) << 5) + 4 * f, evlast);

                float ofa = 1.0f - fa, ofb = 1.0f - fb;
                u64 w00 = bcast2(ofa * ofb);
                u64 w01 = bcast2(ofa * fb);
                u64 w10 = bcast2(fa * ofb);
                u64 w11 = bcast2(fa * fb);
                u64 fa2 = bcast2(fa);
                u64 fb2 = bcast2(fb);

                const int da = (k == 2) ? 1 : 0;  // dim index of fa
                const int db = (k == 0) ? 1 : 2;  // dim index of fb
                #pragma unroll
                for (int hh = 0; hh < 2; hh++) {
                    u64 a00 = hh ? c00.y : c00.x;
                    u64 a01 = hh ? c01.y : c01.x;
                    u64 a10 = hh ? c10.y : c10.x;
                    u64 a11 = hh ? c11.y : c11.x;

                    hq2[hh] = fma2(w00, a00, hq2[hh]);
                    hq2[hh] = fma2(w01, a01, hq2[hh]);
                    hq2[hh] = fma2(w10, a10, hq2[hh]);
                    hq2[hh] = fma2(w11, a11, hq2[hh]);

                    u64 e1 = fma2(neg1_2, a00, a10);
                    u64 e2 = fma2(neg1_2, a01, a11);
                    u64 t1 = fma2(neg1_2, e1, e2);
                    u64 dua = fma2(fb2, t1, e1);
                    u64 e3 = fma2(neg1_2, a00, a01);
                    u64 e4 = fma2(neg1_2, a10, a11);
                    u64 t2 = fma2(neg1_2, e3, e4);
                    u64 dub = fma2(fa2, t2, e3);

                    U2[da][hh] = add2(U2[da][hh], dua);
                    U2[db][hh] = add2(U2[db][hh], dub);
                }
            }

            float h0f, h1f, h2f, h3f;
            unpack2f(hq2[0], h0f, h1f);
            unpack2f(hq2[1], h2f, h3f);

            if (valid) {
                float4 hv = make_float4(h0f, h1f, h2f, h3f);
                __stcs(reinterpret_cast<float4*>(outH + (size_t)p * 32 + 4 * f), hv);
            }

            unsigned hp0 = packh2(__float2half(h0f), __float2half(h1f));
            unsigned hp1 = packh2(__float2half(h2f), __float2half(h3f));
            *reinterpret_cast<uint2*>(st + (4 * r + g) * 40 + 4 * f) = make_uint2(hp0, hp1);

            if (r == 0) {
                ubq[0] = make_ulonglong2(U2[0][0], U2[0][1]);
                ubq[1] = make_ulonglong2(U2[1][0], U2[1][1]);
                ubq[2] = make_ulonglong2(U2[2][0], U2[2][1]);
            }
        }
        __syncwarp();

        // ---------- stage next iteration's x via cp.async (register-free) ----------
        {
            const int nw = warpId + warpStride;
            if (nw * 8 < N) {
                if (f < 3) {
                    #pragma unroll
                    for (int r = 0; r < 2; r++) {
                        int p  = nw * 8 + 4 * r + g;
                        int pc = (p < N) ? p : (N - 1);
                        unsigned dst = (unsigned)__cvta_generic_to_shared(&xstage[buf ^ 1][w][4 * r + g][f]);
                        cp_async4(dst, &x[(size_t)pc * 3 + f]);
                    }
                }
                cp_async_commit();
            }
            buf ^= 1;
        }

        // ---------- forward mma: Z[8,32] = H * W1s ----------
        unsigned aF[2][2];
        #pragma unroll
        for (int kt = 0; kt < 2; kt++) {
            aF[kt][0] = *reinterpret_cast<const unsigned*>(st + gid * 40 + 2 * tig + 16 * kt);
            aF[kt][1] = *reinterpret_cast<const unsigned*>(st + gid * 40 + 2 * tig + 16 * kt + 8);
        }
        unsigned wfb[16];
        *reinterpret_cast<uint4*>(wfb +  0) = wl4[0];
        *reinterpret_cast<uint4*>(wfb +  4) = wl4[1];
        *reinterpret_cast<uint4*>(wfb +  8) = wl4[2];
        *reinterpret_cast<uint4*>(wfb + 12) = wl4[3];
        float dF[4][4];
        #pragma unroll
        for (int nt = 0; nt < 4; nt++) {
            dF[nt][0] = dF[nt][1] = dF[nt][2] = dF[nt][3] = 0.0f;
            #pragma unroll
            for (int kt = 0; kt < 2; kt++)
                mma16816(dF[nt][0], dF[nt][1], dF[nt][2], dF[nt][3],
                         aF[kt][0], 0u, aF[kt][1], 0u,
                         wfb[kt * 8 + nt * 2], wfb[kt * 8 + nt * 2 + 1]);
        }

        // ---------- activation + cotangent (C layout) ----------
        unsigned y2[4], g2[4];
        #pragma unroll
        for (int nt = 0; nt < 4; nt++) {
            __half2 z2 = __floats2half2_rn(dF[nt][0], dF[nt][1]);
            __half2 yb = __hadd2(z2, b1h2[nt]);
            __half2 yl = __hfma2(__hmin2(yb, zero2), slope2, __hmax2(yb, zero2));
            y2[nt] = *reinterpret_cast<unsigned*>(&yl);
            __half2 wneg = __hmul2(slope2, wpos[nt]);
            __half glo = __hlt(__low2half(yb),  hzero) ? __low2half(wneg)  : __low2half(wpos[nt]);
            __half ghi = __hlt(__high2half(yb), hzero) ? __high2half(wneg) : __high2half(wpos[nt]);
            g2[nt] = packh2(glo, ghi);
        }

        // ---------- layer 2: O[8,4] = Y * W2s ----------
        float o0 = 0, o1 = 0, o2d = 0, o3d = 0;
        {
            uint4 w2f = wl4[8];
            mma16816(o0, o1, o2d, o3d, y2[0], 0u, y2[1], 0u, w2f.x, w2f.y);
            mma16816(o0, o1, o2d, o3d, y2[2], 0u, y2[3], 0u, w2f.z, w2f.w);
        }

        // ---------- backward: GH[8,32] = G * W1s^T ----------
        unsigned wbb[16];
        *reinterpret_cast<uint4*>(wbb +  0) = wl4[4];
        *reinterpret_cast<uint4*>(wbb +  4) = wl4[5];
        *reinterpret_cast<uint4*>(wbb +  8) = wl4[6];
        *reinterpret_cast<uint4*>(wbb + 12) = wl4[7];
        float dB[4][4];
        #pragma unroll
        for (int nt = 0; nt < 4; nt++) {
            dB[nt][0] = dB[nt][1] = dB[nt][2] = dB[nt][3] = 0.0f;
            #pragma unroll
            for (int kt = 0; kt < 2; kt++)
                mma16816(dB[nt][0], dB[nt][1], dB[nt][2], dB[nt][3],
                         g2[2 * kt], 0u, g2[2 * kt + 1], 0u,
                         wbb[kt * 8 + nt * 2], wbb[kt * 8 + nt * 2 + 1]);
        }
        __syncwarp();

        #pragma unroll
        for (int nt = 0; nt < 4; nt++) {
            unsigned pk = packh2(__float2half(dB[nt][0]), __float2half(dB[nt][1]));
            *reinterpret_cast<unsigned*>(st + gid * 40 + 8 * nt + 2 * tig) = pk;
        }
        __syncwarp();

        // ---------- nablas: gh . U per pass (f32x2), reduce over 8 lanes ----------
        float nb[2][3];
        #pragma unroll
        for (int r = 0; r < 2; r++) {
            uint2 gw = *reinterpret_cast<const uint2*>(st + (4 * r + g) * 40 + 4 * f);
            float2 g01f = __half22float2(*reinterpret_cast<__half2*>(&gw.x));
            float2 g23f = __half22float2(*reinterpret_cast<__half2*>(&gw.y));
            u64 g01 = pack2(g01f.x, g01f.y);
            u64 g23 = pack2(g23f.x, g23f.y);
            #pragma unroll
            for (int d = 0; d < 3; d++) {
                u64 u0, u1;
                if (r == 0) { ulonglong2 uq = ubq[d]; u0 = uq.x; u1 = uq.y; }
                else        { u0 = U2[d][0]; u1 = U2[d][1]; }
                u64 s2 = fma2(g01, u0, fma2(g23, u1, 0ULL));
                float slo, shi;
                unpack2f(s2, slo, shi);
                nb[r][d] = slo + shi;
            }
        }
        __syncwarp();

        // reduce-scatter over 8 lanes
        {
            float v0 = nb[0][0], v1 = nb[0][1], v2 = nb[0][2], v3 = 0.0f;
            float v4 = nb[1][0], v5 = nb[1][1], v6 = nb[1][2], v7 = 0.0f;
            bool hi4 = (f & 4) != 0;
            float t;
            t = __shfl_xor_sync(FULLM, hi4 ? v0 : v4, 4, 8); if (hi4) v4 += t; else v0 += t;
            t = __shfl_xor_sync(FULLM, hi4 ? v1 : v5, 4, 8); if (hi4) v5 += t; else v1 += t;
            t = __shfl_xor_sync(FULLM, hi4 ? v2 : v6, 4, 8); if (hi4) v6 += t; else v2 += t;
            float w0 = hi4 ? v4 : v0, w1 = hi4 ? v5 : v1, w2 = hi4 ? v6 : v2, w3 = hi4 ? v7 : v3;
            bool hi2 = (f & 2) != 0;
            t = __shfl_xor_sync(FULLM, hi2 ? w0 : w2, 2, 8); if (hi2) w2 += t; else w0 += t;
            t = __shfl_xor_sync(FULLM, hi2 ? w1 : w3, 2, 8); if (hi2) w3 += t; else w1 += t;
            float u0 = hi2 ? w2 : w0, u1 = hi2 ? w3 : w1;
            bool hi1 = (f & 1) != 0;
            t = __shfl_xor_sync(FULLM, hi1 ? u0 : u1, 1, 8); if (hi1) u1 += t; else u0 += t;
            float res = hi1 ? u1 : u0;

            int fm = f & 3;
            if (fm < 3) {
                int pp = base + ((f >> 2) << 2) + g;
                if (pp < N) __stcs(&outNab[(size_t)pp * 3 + fm], res * 511.0f);
            }
        }

        // ---------- sdf / rgb ----------
        if (tig < 2) {
            int pp = base + gid;
            if (pp < N) {
                __half2 oa = __hadd2(__floats2half2_rn(o0, o1), b2p);
                float a0 = __half2float(__low2half(oa));
                float a1 = __half2float(__high2half(oa));
                if (tig == 0) {
                    __stcs(&outSdf[pp], a0);
                    __stcs(&outRgb[(size_t)pp * 3 + 0], (tanhf(a1) + 1.0f) * 0.5f);
                } else {
                    __stcs(&outRgb[(size_t)pp * 3 + 1], (tanhf(a0) + 1.0f) * 0.5f);
                    __stcs(&outRgb[(size_t)pp * 3 + 2], (tanhf(a1) + 1.0f) * 0.5f);
                }
            }
        }
    }
    #undef W1S
    #undef W2S
}

extern "C" void kernel_launch(void* const* d_in, const int* in_sizes, int n_in,
                              void* d_out, int out_size)
{
    const float* x      = (const float*)d_in[0];
    const float* planes = (const float*)d_in[1];
    const float* W1     = (const float*)d_in[2];
    const float* b1     = (const float*)d_in[3];
    const float* W2     = (const float*)d_in[4];
    const float* b2     = (const float*)d_in[5];
    float* out = (float*)d_out;

    int N = in_sizes[0] / 3;

    const int threads = 256;
    const int ptsPerCta = (threads / 32) * 8;  // 64 points per CTA iteration
    int blocksFull = (N + ptsPerCta - 1) / ptsPerCta;
    int blocks = blocksFull < 4736 ? blocksFull : 4736;

    styleneus_fused<<<blocks, threads>>>(x, planes, W1, b1, W2, b2, out, N);
}

// round 15
// speedup vs baseline: 1.2553x; 1.0435x over previous
#include <cuda_runtime.h>
#include <cuda_fp16.h>

#define RESV 512
#define FULLM 0xffffffffu

typedef unsigned long long u64;

__device__ __forceinline__ void mma16816(float& d0, float& d1, float& d2, float& d3,
                                         unsigned a0, unsigned a1, unsigned a2, unsigned a3,
                                         unsigned b0, unsigned b1) {
    asm volatile("mma.sync.aligned.m16n8k16.row.col.f32.f16.f16.f32 "
                 "{%0,%1,%2,%3},{%4,%5,%6,%7},{%8,%9},{%0,%1,%2,%3};"
                 : "+f"(d0), "+f"(d1), "+f"(d2), "+f"(d3)
                 : "r"(a0), "r"(a1), "r"(a2), "r"(a3), "r"(b0), "r"(b1));
}

__device__ __forceinline__ unsigned packh2(__half lo, __half hi) {
    __half2 h = __halves2half2(lo, hi);
    return *reinterpret_cast<unsigned*>(&h);
}

__device__ __forceinline__ u64 mk_evict_last_policy() {
    u64 pol;
    asm("createpolicy.fractional.L2::evict_last.b64 %0, 1.0;" : "=l"(pol));
    return pol;
}

__device__ __forceinline__ void pf_l2(const void* p) {
    asm volatile("prefetch.global.L2 [%0];" :: "l"(p));
}

// ---- packed f32x2 helpers (Blackwell) ----
__device__ __forceinline__ u64 fma2(u64 a, u64 b, u64 c) {
    u64 d; asm("fma.rn.f32x2 %0, %1, %2, %3;" : "=l"(d) : "l"(a), "l"(b), "l"(c));
    return d;
}
__device__ __forceinline__ u64 add2(u64 a, u64 b) {
    u64 d; asm("add.rn.f32x2 %0, %1, %2;" : "=l"(d) : "l"(a), "l"(b));
    return d;
}
__device__ __forceinline__ u64 bcast2(float v) {
    u64 d; asm("mov.b64 %0, {%1, %1};" : "=l"(d) : "f"(v));
    return d;
}
__device__ __forceinline__ u64 pack2(float lo, float hi) {
    u64 d; asm("mov.b64 %0, {%1, %2};" : "=l"(d) : "f"(lo), "f"(hi));
    return d;
}
__device__ __forceinline__ void unpack2f(u64 v, float& lo, float& hi) {
    asm("mov.b64 {%0, %1}, %2;" : "=f"(lo), "=f"(hi) : "l"(v));
}

// 16-byte plane gather as two packed f32x2 words, evict-last hint
__device__ __forceinline__ ulonglong2 ldg_plane2(const float* p, u64 pol) {
    ulonglong2 v;
    asm volatile("ld.global.nc.L2::cache_hint.v2.u64 {%0,%1}, [%2], %3;"
                 : "=l"(v.x), "=l"(v.y) : "l"(p), "l"(pol));
    return v;
}

// compute clamped cell indices from a raw x value
__device__ __forceinline__ void cell_of(float xv, float& fr, int& q0, int& q1) {
    float pos = (xv + 1.0f) * 0.5f * 511.0f;
    float fl  = floorf(pos);
    fr = pos - fl;
    int q = (int)fl;
    q = q < 0 ? 0 : (q > 511 ? 511 : q);
    q0 = q;
    q1 = (q + 1 > 511) ? 511 : (q + 1);
}

__global__ void __launch_bounds__(256, 3)
styleneus_fused(const float* __restrict__ x,
                const float* __restrict__ planes,
                const float* __restrict__ W1,
                const float* __restrict__ b1,
                const float* __restrict__ W2,
                const float* __restrict__ b2,
                float* __restrict__ out,
                int N)
{
    __shared__ unsigned wfrag[32 * 36];
    __shared__ __half stage[8 * 320];
    __shared__ __align__(16) float uback[256 * 12];

    const __half  sh     = __float2half(0.17677669529663689f);  // fp16(1/sqrt(32))
    const __half  hzero  = __float2half(0.0f);
    const __half2 zero2  = __float2half2_rn(0.0f);
    const __half2 slope2 = __float2half2_rn(0.2f);

    const u64 evlast = mk_evict_last_policy();
    const u64 neg1_2 = 0xBF800000BF800000ULL;  // {-1.0f, -1.0f}

    const int tid  = threadIdx.x;
    const int lane = tid & 31;
    const int f    = lane & 7;   // feature-slice (gather layout)
    const int g    = lane >> 3;  // point-in-pass (gather layout)
    const int tig  = lane & 3;   // mma thread-in-group
    const int gid  = lane >> 2;  // mma group id

    #define W1S(i, j) __hmul(__float2half(__ldg(&W1[(i) * 32 + (j)])), sh)
    #define W2S(i, j) __hmul(__float2half(__ldg(&W2[(i) * 4 + (j)])), sh)

    if (tid < 32) {
        unsigned* wl = wfrag + lane * 36;
        #pragma unroll
        for (int kt = 0; kt < 2; kt++)
            #pragma unroll
            for (int nt = 0; nt < 4; nt++) {
                int k0 = 16 * kt + 2 * tig;
                int jc = 8 * nt + gid;
                wl[kt * 8 + nt * 2 + 0] = packh2(W1S(k0,     jc), W1S(k0 + 1, jc));
                wl[kt * 8 + nt * 2 + 1] = packh2(W1S(k0 + 8, jc), W1S(k0 + 9, jc));
                wl[16 + kt * 8 + nt * 2 + 0] = packh2(W1S(jc, k0),     W1S(jc, k0 + 1));
                wl[16 + kt * 8 + nt * 2 + 1] = packh2(W1S(jc, k0 + 8), W1S(jc, k0 + 9));
            }
        #pragma unroll
        for (int kt = 0; kt < 2; kt++) {
            int k0 = 16 * kt + 2 * tig;
            if (gid < 4) {
                wl[32 + kt * 2 + 0] = packh2(W2S(k0,     gid), W2S(k0 + 1, gid));
                wl[32 + kt * 2 + 1] = packh2(W2S(k0 + 8, gid), W2S(k0 + 9, gid));
            } else {
                wl[32 + kt * 2 + 0] = 0;
                wl[32 + kt * 2 + 1] = 0;
            }
        }
    }
    __syncthreads();

    __half2 b1h2[4], wpos[4];
    #pragma unroll
    for (int nt = 0; nt < 4; nt++) {
        int c0 = 8 * nt + 2 * tig;
        b1h2[nt] = __halves2half2(__float2half(__ldg(&b1[c0])), __float2half(__ldg(&b1[c0 + 1])));
        wpos[nt] = __halves2half2(W2S(c0, 0), W2S(c0 + 1, 0));
    }
    __half2 b2p = zero2;
    if (tig < 2)
        b2p = __halves2half2(__float2half(__ldg(&b2[2 * tig])), __float2half(__ldg(&b2[2 * tig + 1])));

    float* __restrict__ outSdf = out;
    float* __restrict__ outH   = out + (size_t)N;
    float* __restrict__ outNab = out + (size_t)N * 33;
    float* __restrict__ outRgb = out + (size_t)N * 36;

    __half* st = stage + (tid >> 5) * 320;
    const uint4* wl4 = reinterpret_cast<const uint4*>(wfrag + lane * 36);
    ulonglong2*  ubq = reinterpret_cast<ulonglong2*>(uback + tid * 12);

    const int warpsPerCta = blockDim.x >> 5;
    int       warpId      = blockIdx.x * warpsPerCta + (tid >> 5);
    const int warpStride  = gridDim.x * warpsPerCta;

    for (; warpId * 8 < N; warpId += warpStride) {
        const int base = warpId * 8;

        // ---------- load coordinates (L1-hit after first iteration: tail preloads) ----------
        float fr2[2][3];
        int   i02[2][3], i12[2][3];
        #pragma unroll
        for (int r = 0; r < 2; r++) {
            int p  = base + 4 * r + g;
            int pc = (p < N) ? p : (N - 1);
            #pragma unroll
            for (int d = 0; d < 3; d++) {
                float xv = __ldg(&x[(size_t)pc * 3 + d]);
                cell_of(xv, fr2[r][d], i02[r][d], i12[r][d]);
            }
        }

        // ---------- prefetch pass-1 gather lines into L2 (short range, proven) ----------
        #pragma unroll
        for (int k = 0; k < 3; k++) {
            const int a = (k == 2) ? 1 : 0;
            const int b = (k == 0) ? 1 : 2;
            const float* pb = planes + (size_t)k * (RESV * RESV * 32);
            int ra0 = i02[1][a] << 9, ra1 = i12[1][a] << 9;
            int cb0 = i02[1][b],      cb1 = i12[1][b];
            pf_l2(pb + (((size_t)(ra0 + cb0)) << 5) + 4 * f);
            pf_l2(pb + (((size_t)(ra0 + cb1)) << 5) + 4 * f);
            pf_l2(pb + (((size_t)(ra1 + cb0)) << 5) + 4 * f);
            pf_l2(pb + (((size_t)(ra1 + cb1)) << 5) + 4 * f);
        }

        // ---------- encode: 2 passes of 4 points, gather layout, f32x2 math ----------
        u64 U2[3][2];
        #pragma unroll
        for (int r = 0; r < 2; r++) {
            int  p     = base + 4 * r + g;
            bool valid = (p < N);

            u64 hq2[2] = {0ULL, 0ULL};
            #pragma unroll
            for (int d = 0; d < 3; d++) { U2[d][0] = 0ULL; U2[d][1] = 0ULL; }

            #pragma unroll
            for (int k = 0; k < 3; k++) {
                const int a = (k == 2) ? 1 : 0;
                const int b = (k == 0) ? 1 : 2;
                float fa = fr2[r][a], fb = fr2[r][b];
                const float* pb = planes + (size_t)k * (RESV * RESV * 32);
                int ra0 = i02[r][a] << 9, ra1 = i12[r][a] << 9;
                int cb0 = i02[r][b],      cb1 = i12[r][b];

                ulonglong2 c00 = ldg_plane2(pb + (((size_t)(ra0 + cb0)) << 5) + 4 * f, evlast);
                ulonglong2 c01 = ldg_plane2(pb + (((size_t)(ra0 + cb1)) << 5) + 4 * f, evlast);
                ulonglong2 c10 = ldg_plane2(pb + (((size_t)(ra1 + cb0)) << 5) + 4 * f, evlast);
                ulonglong2 c11 = ldg_plane2(pb + (((size_t)(ra1 + cb1)) << 5) + 4 * f, evlast);

                float ofa = 1.0f - fa, ofb = 1.0f - fb;
                u64 w00 = bcast2(ofa * ofb);
                u64 w01 = bcast2(ofa * fb);
                u64 w10 = bcast2(fa * ofb);
                u64 w11 = bcast2(fa * fb);
                u64 fa2 = bcast2(fa);
                u64 fb2 = bcast2(fb);

                const int da = (k == 2) ? 1 : 0;  // dim index of fa
                const int db = (k == 0) ? 1 : 2;  // dim index of fb
                #pragma unroll
                for (int hh = 0; hh < 2; hh++) {
                    u64 a00 = hh ? c00.y : c00.x;
                    u64 a01 = hh ? c01.y : c01.x;
                    u64 a10 = hh ? c10.y : c10.x;
                    u64 a11 = hh ? c11.y : c11.x;

                    hq2[hh] = fma2(w00, a00, hq2[hh]);
                    hq2[hh] = fma2(w01, a01, hq2[hh]);
                    hq2[hh] = fma2(w10, a10, hq2[hh]);
                    hq2[hh] = fma2(w11, a11, hq2[hh]);

                    u64 e1 = fma2(neg1_2, a00, a10);
                    u64 e2 = fma2(neg1_2, a01, a11);
                    u64 t1 = fma2(neg1_2, e1, e2);
                    u64 dua = fma2(fb2, t1, e1);
                    u64 e3 = fma2(neg1_2, a00, a01);
                    u64 e4 = fma2(neg1_2, a10, a11);
                    u64 t2 = fma2(neg1_2, e3, e4);
                    u64 dub = fma2(fa2, t2, e3);

                    U2[da][hh] = add2(U2[da][hh], dua);
                    U2[db][hh] = add2(U2[db][hh], dub);
                }
            }

            float h0f, h1f, h2f, h3f;
            unpack2f(hq2[0], h0f, h1f);
            unpack2f(hq2[1], h2f, h3f);

            if (valid) {
                float4 hv = make_float4(h0f, h1f, h2f, h3f);
                __stcs(reinterpret_cast<float4*>(outH + (size_t)p * 32 + 4 * f), hv);
            }

            unsigned hp0 = packh2(__float2half(h0f), __float2half(h1f));
            unsigned hp1 = packh2(__float2half(h2f), __float2half(h3f));
            *reinterpret_cast<uint2*>(st + (4 * r + g) * 40 + 4 * f) = make_uint2(hp0, hp1);

            if (r == 0) {
                ubq[0] = make_ulonglong2(U2[0][0], U2[0][1]);
                ubq[1] = make_ulonglong2(U2[1][0], U2[1][1]);
                ubq[2] = make_ulonglong2(U2[2][0], U2[2][1]);
            }
        }
        __syncwarp();

        // ---------- forward mma: Z[8,32] = H * W1s ----------
        unsigned aF[2][2];
        #pragma unroll
        for (int kt = 0; kt < 2; kt++) {
            aF[kt][0] = *reinterpret_cast<const unsigned*>(st + gid * 40 + 2 * tig + 16 * kt);
            aF[kt][1] = *reinterpret_cast<const unsigned*>(st + gid * 40 + 2 * tig + 16 * kt + 8);
        }
        unsigned wfb[16];
        *reinterpret_cast<uint4*>(wfb +  0) = wl4[0];
        *reinterpret_cast<uint4*>(wfb +  4) = wl4[1];
        *reinterpret_cast<uint4*>(wfb +  8) = wl4[2];
        *reinterpret_cast<uint4*>(wfb + 12) = wl4[3];
        float dF[4][4];
        #pragma unroll
        for (int nt = 0; nt < 4; nt++) {
            dF[nt][0] = dF[nt][1] = dF[nt][2] = dF[nt][3] = 0.0f;
            #pragma unroll
            for (int kt = 0; kt < 2; kt++)
                mma16816(dF[nt][0], dF[nt][1], dF[nt][2], dF[nt][3],
                         aF[kt][0], 0u, aF[kt][1], 0u,
                         wfb[kt * 8 + nt * 2], wfb[kt * 8 + nt * 2 + 1]);
        }

        // ---------- activation + cotangent (C layout) ----------
        unsigned y2[4], g2[4];
        #pragma unroll
        for (int nt = 0; nt < 4; nt++) {
            __half2 z2 = __floats2half2_rn(dF[nt][0], dF[nt][1]);
            __half2 yb = __hadd2(z2, b1h2[nt]);
            __half2 yl = __hfma2(__hmin2(yb, zero2), slope2, __hmax2(yb, zero2));
            y2[nt] = *reinterpret_cast<unsigned*>(&yl);
            __half2 wneg = __hmul2(slope2, wpos[nt]);
            __half glo = __hlt(__low2half(yb),  hzero) ? __low2half(wneg)  : __low2half(wpos[nt]);
            __half ghi = __hlt(__high2half(yb), hzero) ? __high2half(wneg) : __high2half(wpos[nt]);
            g2[nt] = packh2(glo, ghi);
        }

        // ---------- layer 2: O[8,4] = Y * W2s ----------
        float o0 = 0, o1 = 0, o2d = 0, o3d = 0;
        {
            uint4 w2f = wl4[8];
            mma16816(o0, o1, o2d, o3d, y2[0], 0u, y2[1], 0u, w2f.x, w2f.y);
            mma16816(o0, o1, o2d, o3d, y2[2], 0u, y2[3], 0u, w2f.z, w2f.w);
        }

        // ---------- backward: GH[8,32] = G * W1s^T ----------
        unsigned wbb[16];
        *reinterpret_cast<uint4*>(wbb +  0) = wl4[4];
        *reinterpret_cast<uint4*>(wbb +  4) = wl4[5];
        *reinterpret_cast<uint4*>(wbb +  8) = wl4[6];
        *reinterpret_cast<uint4*>(wbb + 12) = wl4[7];
        float dB[4][4];
        #pragma unroll
        for (int nt = 0; nt < 4; nt++) {
            dB[nt][0] = dB[nt][1] = dB[nt][2] = dB[nt][3] = 0.0f;
            #pragma unroll
            for (int kt = 0; kt < 2; kt++)
                mma16816(dB[nt][0], dB[nt][1], dB[nt][2], dB[nt][3],
                         g2[2 * kt], 0u, g2[2 * kt + 1], 0u,
                         wbb[kt * 8 + nt * 2], wbb[kt * 8 + nt * 2 + 1]);
        }
        __syncwarp();

        #pragma unroll
        for (int nt = 0; nt < 4; nt++) {
            unsigned pk = packh2(__float2half(dB[nt][0]), __float2half(dB[nt][1]));
            *reinterpret_cast<unsigned*>(st + gid * 40 + 8 * nt + 2 * tig) = pk;
        }
        __syncwarp();

        // ---------- tail prefetch: next iteration's pass-0 gather lines (~500 cy ahead) ----------
        // Registers here are tail-local only; the __ldg also warms L1 for next loop-top x loads.
        {
            int nw = warpId + warpStride;
            if (nw * 8 < N) {
                int p  = nw * 8 + g;           // next iteration's pass-0 point
                int pc = (p < N) ? p : (N - 1);
                float frd;
                int j0[3], j1[3];
                #pragma unroll
                for (int d = 0; d < 3; d++) {
                    float xv = __ldg(&x[(size_t)pc * 3 + d]);
                    cell_of(xv, frd, j0[d], j1[d]);
                }
                // also touch pass-1's x (warms the line for next loop top)
                int p1  = nw * 8 + 4 + g;
                int pc1 = (p1 < N) ? p1 : (N - 1);
                pf_l2(&x[(size_t)pc1 * 3]);
                #pragma unroll
                for (int k = 0; k < 3; k++) {
                    const int a = (k == 2) ? 1 : 0;
                    const int b = (k == 0) ? 1 : 2;
                    const float* pb = planes + (size_t)k * (RESV * RESV * 32);
                    int ra0 = j0[a] << 9, ra1 = j1[a] << 9;
                    int cb0 = j0[b],      cb1 = j1[b];
                    pf_l2(pb + (((size_t)(ra0 + cb0)) << 5) + 4 * f);
                    pf_l2(pb + (((size_t)(ra0 + cb1)) << 5) + 4 * f);
                    pf_l2(pb + (((size_t)(ra1 + cb0)) << 5) + 4 * f);
                    pf_l2(pb + (((size_t)(ra1 + cb1)) << 5) + 4 * f);
                }
            }
        }

        // ---------- nablas: gh . U per pass (f32x2), reduce over 8 lanes ----------
        float nb[2][3];
        #pragma unroll
        for (int r = 0; r < 2; r++) {
            uint2 gw = *reinterpret_cast<const uint2*>(st + (4 * r + g) * 40 + 4 * f);
            float2 g01f = __half22float2(*reinterpret_cast<__half2*>(&gw.x));
            float2 g23f = __half22float2(*reinterpret_cast<__half2*>(&gw.y));
            u64 g01 = pack2(g01f.x, g01f.y);
            u64 g23 = pack2(g23f.x, g23f.y);
            #pragma unroll
            for (int d = 0; d < 3; d++) {
                u64 u0, u1;
                if (r == 0) { ulonglong2 uq = ubq[d]; u0 = uq.x; u1 = uq.y; }
                else        { u0 = U2[d][0]; u1 = U2[d][1]; }
                u64 s2 = fma2(g01, u0, fma2(g23, u1, 0ULL));
                float slo, shi;
                unpack2f(s2, slo, shi);
                nb[r][d] = slo + shi;
            }
        }
        __syncwarp();

        // reduce-scatter over 8 lanes
        {
            float v0 = nb[0][0], v1 = nb[0][1], v2 = nb[0][2], v3 = 0.0f;
            float v4 = nb[1][0], v5 = nb[1][1], v6 = nb[1][2], v7 = 0.0f;
            bool hi4 = (f & 4) != 0;
            float t;
            t = __shfl_xor_sync(FULLM, hi4 ? v0 : v4, 4, 8); if (hi4) v4 += t; else v0 += t;
            t = __shfl_xor_sync(FULLM, hi4 ? v1 : v5, 4, 8); if (hi4) v5 += t; else v1 += t;
            t = __shfl_xor_sync(FULLM, hi4 ? v2 : v6, 4, 8); if (hi4) v6 += t; else v2 += t;
            float w0 = hi4 ? v4 : v0, w1 = hi4 ? v5 : v1, w2 = hi4 ? v6 : v2, w3 = hi4 ? v7 : v3;
            bool hi2 = (f & 2) != 0;
            t = __shfl_xor_sync(FULLM, hi2 ? w0 : w2, 2, 8); if (hi2) w2 += t; else w0 += t;
            t = __shfl_xor_sync(FULLM, hi2 ? w1 : w3, 2, 8); if (hi2) w3 += t; else w1 += t;
            float u0 = hi2 ? w2 : w0, u1 = hi2 ? w3 : w1;
            bool hi1 = (f & 1) != 0;
            t = __shfl_xor_sync(FULLM, hi1 ? u0 : u1, 1, 8); if (hi1) u1 += t; else u0 += t;
            float res = hi1 ? u1 : u0;

            int fm = f & 3;
            if (fm < 3) {
                int pp = base + ((f >> 2) << 2) + g;
                if (pp < N) __stcs(&outNab[(size_t)pp * 3 + fm], res * 511.0f);
            }
        }

        // ---------- sdf / rgb ----------
        if (tig < 2) {
            int pp = base + gid;
            if (pp < N) {
                __half2 oa = __hadd2(__floats2half2_rn(o0, o1), b2p);
                float a0 = __half2float(__low2half(oa));
                float a1 = __half2float(__high2half(oa));
                if (tig == 0) {
                    __stcs(&outSdf[pp], a0);
                    __stcs(&outRgb[(size_t)pp * 3 + 0], (tanhf(a1) + 1.0f) * 0.5f);
                } else {
                    __stcs(&outRgb[(size_t)pp * 3 + 1], (tanhf(a0) + 1.0f) * 0.5f);
                    __stcs(&outRgb[(size_t)pp * 3 + 2], (tanhf(a1) + 1.0f) * 0.5f);
                }
            }
        }
    }
    #undef W1S
    #undef W2S
}

extern "C" void kernel_launch(void* const* d_in, const int* in_sizes, int n_in,
                              void* d_out, int out_size)
{
    const float* x      = (const float*)d_in[0];
    const float* planes = (const float*)d_in[1];
    const float* W1     = (const float*)d_in[2];
    const float* b1     = (const float*)d_in[3];
    const float* W2     = (const float*)d_in[4];
    const float* b2     = (const float*)d_in[5];
    float* out = (float*)d_out;

    int N = in_sizes[0] / 3;

    const int threads = 256;
    const int ptsPerCta = (threads / 32) * 8;  // 64 points per CTA iteration
    int blocksFull = (N + ptsPerCta - 1) / ptsPerCta;
    int blocks = blocksFull < 4736 ? blocksFull : 4736;

    styleneus_fused<<<blocks, threads>>>(x, planes, W1, b1, W2, b2, out, N);
}

// round 16
// speedup vs baseline: 1.2667x; 1.0091x over previous
#include <cuda_runtime.h>
#include <cuda_fp16.h>

#define RESV 512
#define FULLM 0xffffffffu

typedef unsigned long long u64;

__device__ __forceinline__ void mma16816(float& d0, float& d1, float& d2, float& d3,
                                         unsigned a0, unsigned a1, unsigned a2, unsigned a3,
                                         unsigned b0, unsigned b1) {
    asm volatile("mma.sync.aligned.m16n8k16.row.col.f32.f16.f16.f32 "
                 "{%0,%1,%2,%3},{%4,%5,%6,%7},{%8,%9},{%0,%1,%2,%3};"
                 : "+f"(d0), "+f"(d1), "+f"(d2), "+f"(d3)
                 : "r"(a0), "r"(a1), "r"(a2), "r"(a3), "r"(b0), "r"(b1));
}

__device__ __forceinline__ unsigned packh2(__half lo, __half hi) {
    __half2 h = __halves2half2(lo, hi);
    return *reinterpret_cast<unsigned*>(&h);
}

__device__ __forceinline__ u64 mk_evict_last_policy() {
    u64 pol;
    asm("createpolicy.fractional.L2::evict_last.b64 %0, 1.0;" : "=l"(pol));
    return pol;
}

__device__ __forceinline__ void pf_l2(const void* p) {
    asm volatile("prefetch.global.L2 [%0];" :: "l"(p));
}

// ---- packed f32x2 helpers (Blackwell) ----
__device__ __forceinline__ u64 fma2(u64 a, u64 b, u64 c) {
    u64 d; asm("fma.rn.f32x2 %0, %1, %2, %3;" : "=l"(d) : "l"(a), "l"(b), "l"(c));
    return d;
}
__device__ __forceinline__ u64 add2(u64 a, u64 b) {
    u64 d; asm("add.rn.f32x2 %0, %1, %2;" : "=l"(d) : "l"(a), "l"(b));
    return d;
}
__device__ __forceinline__ u64 bcast2(float v) {
    u64 d; asm("mov.b64 %0, {%1, %1};" : "=l"(d) : "f"(v));
    return d;
}
__device__ __forceinline__ u64 pack2(float lo, float hi) {
    u64 d; asm("mov.b64 %0, {%1, %2};" : "=l"(d) : "f"(lo), "f"(hi));
    return d;
}
__device__ __forceinline__ void unpack2f(u64 v, float& lo, float& hi) {
    asm("mov.b64 {%0, %1}, %2;" : "=f"(lo), "=f"(hi) : "l"(v));
}

// 16-byte plane gather as two packed f32x2 words, evict-last hint
__device__ __forceinline__ ulonglong2 ldg_plane2(const float* p, u64 pol) {
    ulonglong2 v;
    asm volatile("ld.global.nc.L2::cache_hint.v2.u64 {%0,%1}, [%2], %3;"
                 : "=l"(v.x), "=l"(v.y) : "l"(p), "l"(pol));
    return v;
}

// compute clamped cell indices from a raw x value
__device__ __forceinline__ void cell_of(float xv, float& fr, int& q0, int& q1) {
    float pos = (xv + 1.0f) * 0.5f * 511.0f;
    float fl  = floorf(pos);
    fr = pos - fl;
    int q = (int)fl;
    q = q < 0 ? 0 : (q > 511 ? 511 : q);
    q0 = q;
    q1 = (q + 1 > 511) ? 511 : (q + 1);
}

__global__ void __launch_bounds__(256, 3)
styleneus_fused(const float* __restrict__ x,
                const float* __restrict__ planes,
                const float* __restrict__ W1,
                const float* __restrict__ b1,
                const float* __restrict__ W2,
                const float* __restrict__ b2,
                float* __restrict__ out,
                int N)
{
    __shared__ unsigned wfrag[32 * 36];
    __shared__ __half stage[8 * 320];
    __shared__ __align__(16) float uback[256 * 12];

    const __half  sh     = __float2half(0.17677669529663689f);  // fp16(1/sqrt(32))
    const __half  hzero  = __float2half(0.0f);
    const __half2 zero2  = __float2half2_rn(0.0f);
    const __half2 slope2 = __float2half2_rn(0.2f);

    const u64 evlast = mk_evict_last_policy();
    const u64 neg1_2 = 0xBF800000BF800000ULL;  // {-1.0f, -1.0f}

    const int tid  = threadIdx.x;
    const int lane = tid & 31;
    const int f    = lane & 7;   // feature-slice (gather layout)
    const int g    = lane >> 3;  // point-in-pass (gather layout)
    const int tig  = lane & 3;   // mma thread-in-group
    const int gid  = lane >> 2;  // mma group id

    #define W1S(i, j) __hmul(__float2half(__ldg(&W1[(i) * 32 + (j)])), sh)
    #define W2S(i, j) __hmul(__float2half(__ldg(&W2[(i) * 4 + (j)])), sh)

    if (tid < 32) {
        unsigned* wl = wfrag + lane * 36;
        #pragma unroll
        for (int kt = 0; kt < 2; kt++)
            #pragma unroll
            for (int nt = 0; nt < 4; nt++) {
                int k0 = 16 * kt + 2 * tig;
                int jc = 8 * nt + gid;
                wl[kt * 8 + nt * 2 + 0] = packh2(W1S(k0,     jc), W1S(k0 + 1, jc));
                wl[kt * 8 + nt * 2 + 1] = packh2(W1S(k0 + 8, jc), W1S(k0 + 9, jc));
                wl[16 + kt * 8 + nt * 2 + 0] = packh2(W1S(jc, k0),     W1S(jc, k0 + 1));
                wl[16 + kt * 8 + nt * 2 + 1] = packh2(W1S(jc, k0 + 8), W1S(jc, k0 + 9));
            }
        #pragma unroll
        for (int kt = 0; kt < 2; kt++) {
            int k0 = 16 * kt + 2 * tig;
            if (gid < 4) {
                wl[32 + kt * 2 + 0] = packh2(W2S(k0,     gid), W2S(k0 + 1, gid));
                wl[32 + kt * 2 + 1] = packh2(W2S(k0 + 8, gid), W2S(k0 + 9, gid));
            } else {
                wl[32 + kt * 2 + 0] = 0;
                wl[32 + kt * 2 + 1] = 0;
            }
        }
    }
    __syncthreads();

    __half2 b1h2[4], wpos[4];
    #pragma unroll
    for (int nt = 0; nt < 4; nt++) {
        int c0 = 8 * nt + 2 * tig;
        b1h2[nt] = __halves2half2(__float2half(__ldg(&b1[c0])), __float2half(__ldg(&b1[c0 + 1])));
        wpos[nt] = __halves2half2(W2S(c0, 0), W2S(c0 + 1, 0));
    }
    __half2 b2p = zero2;
    if (tig < 2)
        b2p = __halves2half2(__float2half(__ldg(&b2[2 * tig])), __float2half(__ldg(&b2[2 * tig + 1])));

    float* __restrict__ outSdf = out;
    float* __restrict__ outH   = out + (size_t)N;
    float* __restrict__ outNab = out + (size_t)N * 33;
    float* __restrict__ outRgb = out + (size_t)N * 36;

    __half* st = stage + (tid >> 5) * 320;
    const uint4* wl4 = reinterpret_cast<const uint4*>(wfrag + lane * 36);
    ulonglong2*  ubq = reinterpret_cast<ulonglong2*>(uback + tid * 12);

    const int warpsPerCta = blockDim.x >> 5;
    int       warpId      = blockIdx.x * warpsPerCta + (tid >> 5);
    const int warpStride  = gridDim.x * warpsPerCta;

    for (; warpId * 8 < N; warpId += warpStride) {
        const int base = warpId * 8;

        // ---------- load coordinates ----------
        float fr2[2][3];
        int   i02[2][3], i12[2][3];
        #pragma unroll
        for (int r = 0; r < 2; r++) {
            int p  = base + 4 * r + g;
            int pc = (p < N) ? p : (N - 1);
            #pragma unroll
            for (int d = 0; d < 3; d++) {
                float xv = __ldcs(&x[pc * 3 + d]);
                cell_of(xv, fr2[r][d], i02[r][d], i12[r][d]);
            }
        }

        // ---------- prefetch pass-1 gather lines into L2 (short range, proven) ----------
        #pragma unroll
        for (int k = 0; k < 3; k++) {
            const int a = (k == 2) ? 1 : 0;
            const int b = (k == 0) ? 1 : 2;
            const float* pb = planes + (size_t)k * (RESV * RESV * 32);
            int ra0 = i02[1][a] << 9, ra1 = i12[1][a] << 9;
            int cb0 = i02[1][b],      cb1 = i12[1][b];
            pf_l2(pb + (((size_t)(ra0 + cb0)) << 5) + 4 * f);
            pf_l2(pb + (((size_t)(ra0 + cb1)) << 5) + 4 * f);
            pf_l2(pb + (((size_t)(ra1 + cb0)) << 5) + 4 * f);
            pf_l2(pb + (((size_t)(ra1 + cb1)) << 5) + 4 * f);
        }

        // ---------- issue next-iteration x line prefetch ----------
        {
            int nw = warpId + warpStride;
            if (nw * 8 < N) pf_l2(&x[(size_t)(nw * 8 + g) * 3]);
        }

        // ---------- encode: 2 passes of 4 points, gather layout, f32x2 math ----------
        u64 U2[3][2];
        #pragma unroll
        for (int r = 0; r < 2; r++) {
            int  p     = base + 4 * r + g;
            bool valid = (p < N);

            u64 hq2[2] = {0ULL, 0ULL};
            #pragma unroll
            for (int d = 0; d < 3; d++) { U2[d][0] = 0ULL; U2[d][1] = 0ULL; }

            #pragma unroll
            for (int k = 0; k < 3; k++) {
                const int a = (k == 2) ? 1 : 0;
                const int b = (k == 0) ? 1 : 2;
                float fa = fr2[r][a], fb = fr2[r][b];
                const float* pb = planes + (size_t)k * (RESV * RESV * 32);
                int ra0 = i02[r][a] << 9, ra1 = i12[r][a] << 9;
                int cb0 = i02[r][b],      cb1 = i12[r][b];

                ulonglong2 c00 = ldg_plane2(pb + (((size_t)(ra0 + cb0)) << 5) + 4 * f, evlast);
                ulonglong2 c01 = ldg_plane2(pb + (((size_t)(ra0 + cb1)) << 5) + 4 * f, evlast);
                ulonglong2 c10 = ldg_plane2(pb + (((size_t)(ra1 + cb0)) << 5) + 4 * f, evlast);
                ulonglong2 c11 = ldg_plane2(pb + (((size_t)(ra1 + cb1)) << 5) + 4 * f, evlast);

                float ofa = 1.0f - fa, ofb = 1.0f - fb;
                u64 w00 = bcast2(ofa * ofb);
                u64 w01 = bcast2(ofa * fb);
                u64 w10 = bcast2(fa * ofb);
                u64 w11 = bcast2(fa * fb);
                u64 fa2 = bcast2(fa);
                u64 fb2 = bcast2(fb);

                const int da = (k == 2) ? 1 : 0;  // dim index of fa
                const int db = (k == 0) ? 1 : 2;  // dim index of fb
                #pragma unroll
                for (int hh = 0; hh < 2; hh++) {
                    u64 a00 = hh ? c00.y : c00.x;
                    u64 a01 = hh ? c01.y : c01.x;
                    u64 a10 = hh ? c10.y : c10.x;
                    u64 a11 = hh ? c11.y : c11.x;

                    hq2[hh] = fma2(w00, a00, hq2[hh]);
                    hq2[hh] = fma2(w01, a01, hq2[hh]);
                    hq2[hh] = fma2(w10, a10, hq2[hh]);
                    hq2[hh] = fma2(w11, a11, hq2[hh]);

                    u64 e1 = fma2(neg1_2, a00, a10);
                    u64 e2 = fma2(neg1_2, a01, a11);
                    u64 t1 = fma2(neg1_2, e1, e2);
                    u64 dua = fma2(fb2, t1, e1);
                    u64 e3 = fma2(neg1_2, a00, a01);
                    u64 e4 = fma2(neg1_2, a10, a11);
                    u64 t2 = fma2(neg1_2, e3, e4);
                    u64 dub = fma2(fa2, t2, e3);

                    U2[da][hh] = add2(U2[da][hh], dua);
                    U2[db][hh] = add2(U2[db][hh], dub);
                }
            }

            float h0f, h1f, h2f, h3f;
            unpack2f(hq2[0], h0f, h1f);
            unpack2f(hq2[1], h2f, h3f);

            if (valid) {
                float4 hv = make_float4(h0f, h1f, h2f, h3f);
                __stcs(reinterpret_cast<float4*>(outH + (size_t)p * 32 + 4 * f), hv);
            }

            unsigned hp0 = packh2(__float2half(h0f), __float2half(h1f));
            unsigned hp1 = packh2(__float2half(h2f), __float2half(h3f));
            *reinterpret_cast<uint2*>(st + (4 * r + g) * 40 + 4 * f) = make_uint2(hp0, hp1);

            if (r == 0) {
                ubq[0] = make_ulonglong2(U2[0][0], U2[0][1]);
                ubq[1] = make_ulonglong2(U2[1][0], U2[1][1]);
                ubq[2] = make_ulonglong2(U2[2][0], U2[2][1]);
            }
        }
        __syncwarp();

        // ---------- forward mma: Z[8,32] = H * W1s ----------
        unsigned aF[2][2];
        #pragma unroll
        for (int kt = 0; kt < 2; kt++) {
            aF[kt][0] = *reinterpret_cast<const unsigned*>(st + gid * 40 + 2 * tig + 16 * kt);
            aF[kt][1] = *reinterpret_cast<const unsigned*>(st + gid * 40 + 2 * tig + 16 * kt + 8);
        }
        unsigned wfb[16];
        *reinterpret_cast<uint4*>(wfb +  0) = wl4[0];
        *reinterpret_cast<uint4*>(wfb +  4) = wl4[1];
        *reinterpret_cast<uint4*>(wfb +  8) = wl4[2];
        *reinterpret_cast<uint4*>(wfb + 12) = wl4[3];
        float dF[4][4];
        #pragma unroll
        for (int nt = 0; nt < 4; nt++) {
            dF[nt][0] = dF[nt][1] = dF[nt][2] = dF[nt][3] = 0.0f;
            #pragma unroll
            for (int kt = 0; kt < 2; kt++)
                mma16816(dF[nt][0], dF[nt][1], dF[nt][2], dF[nt][3],
                         aF[kt][0], 0u, aF[kt][1], 0u,
                         wfb[kt * 8 + nt * 2], wfb[kt * 8 + nt * 2 + 1]);
        }

        // ---------- activation + cotangent (C layout) ----------
        unsigned y2[4], g2[4];
        #pragma unroll
        for (int nt = 0; nt < 4; nt++) {
            __half2 z2 = __floats2half2_rn(dF[nt][0], dF[nt][1]);
            __half2 yb = __hadd2(z2, b1h2[nt]);
            __half2 yl = __hfma2(__hmin2(yb, zero2), slope2, __hmax2(yb, zero2));
            y2[nt] = *reinterpret_cast<unsigned*>(&yl);
            __half2 wneg = __hmul2(slope2, wpos[nt]);
            __half glo = __hlt(__low2half(yb),  hzero) ? __low2half(wneg)  : __low2half(wpos[nt]);
            __half ghi = __hlt(__high2half(yb), hzero) ? __high2half(wneg) : __high2half(wpos[nt]);
            g2[nt] = packh2(glo, ghi);
        }

        // ---------- layer 2: O[8,4] = Y * W2s ----------
        float o0 = 0, o1 = 0, o2d = 0, o3d = 0;
        {
            uint4 w2f = wl4[8];
            mma16816(o0, o1, o2d, o3d, y2[0], 0u, y2[1], 0u, w2f.x, w2f.y);
            mma16816(o0, o1, o2d, o3d, y2[2], 0u, y2[3], 0u, w2f.z, w2f.w);
        }

        // ---------- backward: GH[8,32] = G * W1s^T ----------
        unsigned wbb[16];
        *reinterpret_cast<uint4*>(wbb +  0) = wl4[4];
        *reinterpret_cast<uint4*>(wbb +  4) = wl4[5];
        *reinterpret_cast<uint4*>(wbb +  8) = wl4[6];
        *reinterpret_cast<uint4*>(wbb + 12) = wl4[7];
        float dB[4][4];
        #pragma unroll
        for (int nt = 0; nt < 4; nt++) {
            dB[nt][0] = dB[nt][1] = dB[nt][2] = dB[nt][3] = 0.0f;
            #pragma unroll
            for (int kt = 0; kt < 2; kt++)
                mma16816(dB[nt][0], dB[nt][1], dB[nt][2], dB[nt][3],
                         g2[2 * kt], 0u, g2[2 * kt + 1], 0u,
                         wbb[kt * 8 + nt * 2], wbb[kt * 8 + nt * 2 + 1]);
        }
        __syncwarp();

        #pragma unroll
        for (int nt = 0; nt < 4; nt++) {
            unsigned pk = packh2(__float2half(dB[nt][0]), __float2half(dB[nt][1]));
            *reinterpret_cast<unsigned*>(st + gid * 40 + 8 * nt + 2 * tig) = pk;
        }
        __syncwarp();

        // ---------- nablas: gh . U per pass (f32x2), reduce over 8 lanes ----------
        float nb[2][3];
        #pragma unroll
        for (int r = 0; r < 2; r++) {
            uint2 gw = *reinterpret_cast<const uint2*>(st + (4 * r + g) * 40 + 4 * f);
            float2 g01f = __half22float2(*reinterpret_cast<__half2*>(&gw.x));
            float2 g23f = __half22float2(*reinterpret_cast<__half2*>(&gw.y));
            u64 g01 = pack2(g01f.x, g01f.y);
            u64 g23 = pack2(g23f.x, g23f.y);
            #pragma unroll
            for (int d = 0; d < 3; d++) {
                u64 u0, u1;
                if (r == 0) { ulonglong2 uq = ubq[d]; u0 = uq.x; u1 = uq.y; }
                else        { u0 = U2[d][0]; u1 = U2[d][1]; }
                u64 s2 = fma2(g01, u0, fma2(g23, u1, 0ULL));
                float slo, shi;
                unpack2f(s2, slo, shi);
                nb[r][d] = slo + shi;
            }
        }
        __syncwarp();

        // reduce-scatter over 8 lanes
        {
            float v0 = nb[0][0], v1 = nb[0][1], v2 = nb[0][2], v3 = 0.0f;
            float v4 = nb[1][0], v5 = nb[1][1], v6 = nb[1][2], v7 = 0.0f;
            bool hi4 = (f & 4) != 0;
            float t;
            t = __shfl_xor_sync(FULLM, hi4 ? v0 : v4, 4, 8); if (hi4) v4 += t; else v0 += t;
            t = __shfl_xor_sync(FULLM, hi4 ? v1 : v5, 4, 8); if (hi4) v5 += t; else v1 += t;
            t = __shfl_xor_sync(FULLM, hi4 ? v2 : v6, 4, 8); if (hi4) v6 += t; else v2 += t;
            float w0 = hi4 ? v4 : v0, w1 = hi4 ? v5 : v1, w2 = hi4 ? v6 : v2, w3 = hi4 ? v7 : v3;
            bool hi2 = (f & 2) != 0;
            t = __shfl_xor_sync(FULLM, hi2 ? w0 : w2, 2, 8); if (hi2) w2 += t; else w0 += t;
            t = __shfl_xor_sync(FULLM, hi2 ? w1 : w3, 2, 8); if (hi2) w3 += t; else w1 += t;
            float u0 = hi2 ? w2 : w0, u1 = hi2 ? w3 : w1;
            bool hi1 = (f & 1) != 0;
            t = __shfl_xor_sync(FULLM, hi1 ? u0 : u1, 1, 8); if (hi1) u1 += t; else u0 += t;
            float res = hi1 ? u1 : u0;

            int fm = f & 3;
            if (fm < 3) {
                int pp = base + ((f >> 2) << 2) + g;
                if (pp < N) __stcs(&outNab[(size_t)pp * 3 + fm], res * 511.0f);
            }
        }

        // ---------- sdf / rgb ----------
        if (tig < 2) {
            int pp = base + gid;
            if (pp < N) {
                __half2 oa = __hadd2(__floats2half2_rn(o0, o1), b2p);
                float a0 = __half2float(__low2half(oa));
                float a1 = __half2float(__high2half(oa));
                if (tig == 0) {
                    __stcs(&outSdf[pp], a0);
                    __stcs(&outRgb[(size_t)pp * 3 + 0], (tanhf(a1) + 1.0f) * 0.5f);
                } else {
                    __stcs(&outRgb[(size_t)pp * 3 + 1], (tanhf(a0) + 1.0f) * 0.5f);
                    __stcs(&outRgb[(size_t)pp * 3 + 2], (tanhf(a1) + 1.0f) * 0.5f);
                }
            }
        }
    }
    #undef W1S
    #undef W2S
}

extern "C" void kernel_launch(void* const* d_in, const int* in_sizes, int n_in,
                              void* d_out, int out_size)
{
    const float* x      = (const float*)d_in[0];
    const float* planes = (const float*)d_in[1];
    const float* W1     = (const float*)d_in[2];
    const float* b1     = (const float*)d_in[3];
    const float* W2     = (const float*)d_in[4];
    const float* b2     = (const float*)d_in[5];
    float* out = (float*)d_out;

    int N = in_sizes[0] / 3;

    const int threads = 256;
    const int ptsPerCta = (threads / 32) * 8;  // 64 points per CTA iteration
    int blocksFull = (N + ptsPerCta - 1) / ptsPerCta;
    // persistent grid: exactly one wave (148 SMs x 3 resident CTAs)
    int blocks = blocksFull < 444 ? blocksFull : 444;

    styleneus_fused<<<blocks, threads>>>(x, planes, W1, b1, W2, b2, out, N);
}